// round 2
// baseline (speedup 1.0000x reference)
#include <cuda_runtime.h>
#include <stdint.h>

// ---------------- problem constants ----------------
#define N_CLASSES 6000
#define ATT       1024
#define G         15
#define GM1       14          // groups actually written (k=1..14 -> variants 2..15)
#define LP1       16          // rows per class
#define GSIZE     64
#define N_UNSEEN  1200
#define N_SEEN    4800

// ---------------- device scratch (no allocs allowed) ----------------
__device__ uint32_t d_mask16[ATT];            // bit v set => column in group of variant v (v=2..15)
__device__ int      d_nd[LP1];                // distinct masked column count per variant
__device__ float    d_inv[N_CLASSES * LP1];   // 1/norm per (class, variant)

// ---------------- kernel A: build column mask + distinct counts ----------------
__global__ void setup_kernel(const int* __restrict__ gc)
{
    int tid = threadIdx.x;
    if (tid < ATT) d_mask16[tid] = 0u;
    __syncthreads();
    if (tid < GM1 * GSIZE) {
        int k   = tid >> 6;          // group 0..13 -> variant k+2
        int col = gc[tid];
        atomicOr(&d_mask16[col], 1u << (k + 2));
    }
    __syncthreads();
    if (tid < LP1) {
        int cnt = 0;
        if (tid >= 2) {
            for (int j = 0; j < ATT; j++)
                cnt += (int)((d_mask16[j] >> tid) & 1u);
        }
        d_nd[tid] = cnt;
    }
}

// ---------------- kernel B: per-(class,variant) inverse norms ----------------
// ||row_v||^2 = sum(a^2) - sum_{masked cols} a^2 + n_distinct * beta^2
__global__ void norm_kernel(const float* __restrict__ attr,
                            const float* __restrict__ betas)
{
    const int c   = blockIdx.x;
    const int tid = threadIdx.x;            // 256 threads
    const float* row = attr + (size_t)c * ATT;

    float total = 0.f;
    float ms[GM1];
    #pragma unroll
    for (int s = 0; s < GM1; s++) ms[s] = 0.f;

    for (int j = tid; j < ATT; j += 256) {
        float x  = row[j];
        float x2 = x * x;
        total += x2;
        uint32_t mb = d_mask16[j] >> 2;     // bits 0..13 = variants 2..15
        #pragma unroll
        for (int s = 0; s < GM1; s++)
            if ((mb >> s) & 1u) ms[s] += x2;
    }

    __shared__ float red[256 * 17];         // 15 sums, padded stride 17 vs bank conflicts
    #pragma unroll
    for (int s = 0; s < GM1; s++) red[tid * 17 + s] = ms[s];
    red[tid * 17 + 14] = total;
    __syncthreads();

    for (int stride = 128; stride > 0; stride >>= 1) {
        if (tid < stride) {
            #pragma unroll
            for (int s = 0; s < 15; s++)
                red[tid * 17 + s] += red[(tid + stride) * 17 + s];
        }
        __syncthreads();
    }

    if (tid < LP1) {
        float tot = red[14];
        float n2;
        if (tid < 2) {
            n2 = tot;
        } else {
            float b = __ldg(betas + (tid - 2));
            n2 = tot - red[tid - 2] + (float)d_nd[tid] * b * b;
        }
        n2 = fmaxf(n2, 0.f);
        float nrm = fmaxf(sqrtf(n2), 1e-12f);
        d_inv[(size_t)c * LP1 + tid] = 1.f / nrm;
    }
}

// ---------------- kernel C: the big transposed write pass ----------------
// out region layout: [ATT, npos*16] row-major. Thread = (column a, class pos),
// writes 16 contiguous floats (the 16 variants) as 4x float4.
__global__ void write_kernel(const float* __restrict__ attr,
                             const float* __restrict__ betas,
                             const int*   __restrict__ classes,   // nullptr => identity
                             float*       __restrict__ out,
                             int npos)
{
    const int pos = blockIdx.x * blockDim.x + threadIdx.x;
    const int a   = blockIdx.y;
    if (pos >= npos) return;

    const int c = classes ? __ldg(classes + pos) : pos;
    const float    av = __ldg(attr + (size_t)c * ATT + a);
    const uint32_t mb = d_mask16[a];                 // uniform per block
    const float4* invp = (const float4*)(d_inv + (size_t)c * LP1);

    float4* o4 = (float4*)(out + (size_t)a * ((size_t)npos * LP1)
                               + (size_t)pos * LP1);
    #pragma unroll
    for (int q = 0; q < 4; q++) {
        float4 iv = invp[q];
        float ivv[4] = {iv.x, iv.y, iv.z, iv.w};
        float r[4];
        #pragma unroll
        for (int s = 0; s < 4; s++) {
            int v = q * 4 + s;
            float bv = (v >= 2) ? __ldg(betas + (v - 2)) : 0.f;
            r[s] = ((mb >> v) & 1u) ? bv * ivv[s] : av * ivv[s];
        }
        float4 w; w.x = r[0]; w.y = r[1]; w.z = r[2]; w.w = r[3];
        o4[q] = w;
    }
}

// ---------------- launcher ----------------
extern "C" void kernel_launch(void* const* d_in, const int* in_sizes, int n_in,
                              void* d_out, int out_size)
{
    const float* attr   = (const float*)d_in[0];   // [6000,1024] f32
    const float* betas  = (const float*)d_in[1];   // [1,15] f32 (first 14 used)
    const int*   gc     = (const int*)  d_in[2];   // [14,64] i32
    const int*   unseen = (const int*)  d_in[3];   // [1200] i32
    const int*   seen   = (const int*)  d_in[4];   // [4800] i32
    float* out = (float*)d_out;

    setup_kernel<<<1, 1024>>>(gc);
    norm_kernel<<<N_CLASSES, 256>>>(attr, betas);

    float* o_zsl  = out;
    float* o_seen = o_zsl  + (size_t)ATT * N_UNSEEN  * LP1;
    float* o_gzsl = o_seen + (size_t)ATT * N_SEEN    * LP1;

    const int TB = 256;
    write_kernel<<<dim3((N_UNSEEN  + TB - 1) / TB, ATT), TB>>>(attr, betas, unseen,  o_zsl,  N_UNSEEN);
    write_kernel<<<dim3((N_SEEN    + TB - 1) / TB, ATT), TB>>>(attr, betas, seen,    o_seen, N_SEEN);
    write_kernel<<<dim3((N_CLASSES + TB - 1) / TB, ATT), TB>>>(attr, betas, nullptr, o_gzsl, N_CLASSES);
}

// round 5
// speedup vs baseline: 2.2167x; 2.2167x over previous
#include <cuda_runtime.h>
#include <stdint.h>

// ---------------- problem constants ----------------
#define N_CLASSES 6000
#define ATT       1024
#define G         15
#define GM1       14          // groups actually written (k=1..14 -> variants 2..15)
#define LP1       16          // rows per class
#define GSIZE     64
#define N_UNSEEN  1200
#define N_SEEN    4800

// ---------------- device scratch (no allocs allowed) ----------------
__device__ uint32_t d_mask16[ATT];            // bit v set => column in group of variant v (v=2..15)
__device__ int      d_nd[LP1];                // distinct masked column count per variant
__device__ float    d_inv[N_CLASSES * LP1];   // 1/norm per (class, variant)

// ---------------- kernel A: build column mask + distinct counts ----------------
__global__ void setup_kernel(const int* __restrict__ gc)
{
    int tid = threadIdx.x;
    if (tid < ATT) d_mask16[tid] = 0u;
    __syncthreads();
    if (tid < GM1 * GSIZE) {
        int k   = tid >> 6;          // group 0..13 -> variant k+2
        int col = gc[tid];
        atomicOr(&d_mask16[col], 1u << (k + 2));
    }
    __syncthreads();
    if (tid < LP1) {
        int cnt = 0;
        if (tid >= 2) {
            for (int j = 0; j < ATT; j++)
                cnt += (int)((d_mask16[j] >> tid) & 1u);
        }
        d_nd[tid] = cnt;
    }
}

// ---------------- kernel B: per-(class,variant) inverse norms ----------------
// ||row_v||^2 = sum(a^2) - sum_{masked cols} a^2 + n_distinct * beta^2
__global__ void norm_kernel(const float* __restrict__ attr,
                            const float* __restrict__ betas)
{
    const int c   = blockIdx.x;
    const int tid = threadIdx.x;            // 256 threads
    const float* row = attr + (size_t)c * ATT;

    float total = 0.f;
    float ms[GM1];
    #pragma unroll
    for (int s = 0; s < GM1; s++) ms[s] = 0.f;

    for (int j = tid; j < ATT; j += 256) {
        float x  = row[j];
        float x2 = x * x;
        total += x2;
        uint32_t mb = d_mask16[j] >> 2;     // bits 0..13 = variants 2..15
        #pragma unroll
        for (int s = 0; s < GM1; s++)
            if ((mb >> s) & 1u) ms[s] += x2;
    }

    __shared__ float red[256 * 17];         // 15 sums, padded stride 17 vs bank conflicts
    #pragma unroll
    for (int s = 0; s < GM1; s++) red[tid * 17 + s] = ms[s];
    red[tid * 17 + 14] = total;
    __syncthreads();

    for (int stride = 128; stride > 0; stride >>= 1) {
        if (tid < stride) {
            #pragma unroll
            for (int s = 0; s < 15; s++)
                red[tid * 17 + s] += red[(tid + stride) * 17 + s];
        }
        __syncthreads();
    }

    if (tid < LP1) {
        float tot = red[14];
        float n2;
        if (tid < 2) {
            n2 = tot;
        } else {
            float b = __ldg(betas + (tid - 2));
            n2 = tot - red[tid - 2] + (float)d_nd[tid] * b * b;
        }
        n2 = fmaxf(n2, 0.f);
        float nrm = fmaxf(sqrtf(n2), 1e-12f);
        d_inv[(size_t)c * LP1 + tid] = 1.f / nrm;
    }
}

// ---------------- kernel C: tiled transposed write pass (fused 3 regions) ----
// Block = 32 positions x 32 attribute columns. Stage attr tile + inv tile in
// smem with coalesced loads, then write fully-coalesced float4 runs along the
// contiguous (pos,variant) output dimension. blockIdx.z selects the region
// (0=zsl, 1=seen, 2=gzsl). NOTE: 1200 and 6000 are NOT multiples of 32, so
// partial tiles are real — staging clamps to class 0, stores are guarded.
__global__ __launch_bounds__(256) void write_kernel(
        const float* __restrict__ attr,
        const float* __restrict__ betas,
        const int*   __restrict__ unseen,
        const int*   __restrict__ seen,
        float*       __restrict__ out)
{
    int npos;
    const int* classes;
    float* base;
    if (blockIdx.z == 0) {
        npos = N_UNSEEN; classes = unseen; base = out;
    } else if (blockIdx.z == 1) {
        npos = N_SEEN;   classes = seen;
        base = out + (size_t)ATT * N_UNSEEN * LP1;
    } else {
        npos = N_CLASSES; classes = nullptr;
        base = out + (size_t)ATT * (N_UNSEEN + N_SEEN) * LP1;
    }
    const int pos0 = blockIdx.x * 32;
    if (pos0 >= npos) return;                 // oversized grid.x for small regions
    const int a0   = blockIdx.y * 32;

    __shared__ int      cls_s[32];
    __shared__ float    attr_s[32][33];      // [pos_local][a_local], padded
    __shared__ float    inv_s[32][16];       // [pos_local][variant]
    __shared__ float    bv_s[16];
    __shared__ uint32_t mb_s[32];

    const int tid  = threadIdx.x;
    const int lane = tid & 31;
    const int w    = tid >> 5;               // warp 0..7

    if (tid < 32) {
        int p = pos0 + tid;
        int c = 0;                           // clamp OOB slots to class 0 (staging only)
        if (p < npos) c = classes ? __ldg(classes + p) : p;
        cls_s[tid] = c;
        mb_s[tid]  = d_mask16[a0 + tid];
    }
    if (tid < 16) bv_s[tid] = (tid >= 2) ? __ldg(betas + (tid - 2)) : 0.f;
    __syncthreads();

    // stage attribute tile: warp w loads rows p = i*8 + w (coalesced 128B)
    #pragma unroll
    for (int i = 0; i < 4; i++) {
        int p = i * 8 + w;
        int c = cls_s[p];
        attr_s[p][lane] = __ldg(attr + (size_t)c * ATT + a0 + lane);
    }
    // stage inv tile: 512 floats, 2 per thread (16-float segments)
    #pragma unroll
    for (int i = 0; i < 2; i++) {
        int t = i * 256 + tid;
        int p = t >> 4, v = t & 15;
        inv_s[p][v] = d_inv[(size_t)cls_s[p] * LP1 + v];
    }
    __syncthreads();

    // write: warp w handles a_local in [4w, 4w+4). For each a, the 32-pos
    // block covers 512 contiguous floats = 128 float4 (4 iters x 32 lanes).
    #pragma unroll
    for (int ai = 0; ai < 4; ai++) {
        const int al = w * 4 + ai;
        const int a  = a0 + al;
        const uint32_t mb = mb_s[al];
        float4* orow = (float4*)(base + (size_t)a * ((size_t)npos * LP1)
                                      + (size_t)pos0 * LP1);
        #pragma unroll
        for (int it = 0; it < 4; it++) {
            const int f4 = it * 32 + lane;
            const int pl = f4 >> 2;          // pos local 0..31
            const int q  = f4 & 3;           // variant quarter
            if (pos0 + pl < npos) {          // partial-tile guard (1200, 6000 not %32)
                const float av = attr_s[pl][al];
                float4 iv = *(const float4*)&inv_s[pl][q * 4];
                float ivv[4] = {iv.x, iv.y, iv.z, iv.w};
                float r[4];
                #pragma unroll
                for (int s = 0; s < 4; s++) {
                    int v = q * 4 + s;
                    r[s] = (((mb >> v) & 1u) ? bv_s[v] : av) * ivv[s];
                }
                float4 wv; wv.x = r[0]; wv.y = r[1]; wv.z = r[2]; wv.w = r[3];
                orow[f4] = wv;
            }
        }
    }
}

// ---------------- launcher ----------------
extern "C" void kernel_launch(void* const* d_in, const int* in_sizes, int n_in,
                              void* d_out, int out_size)
{
    const float* attr   = (const float*)d_in[0];   // [6000,1024] f32
    const float* betas  = (const float*)d_in[1];   // [1,15] f32 (first 14 used)
    const int*   gc     = (const int*)  d_in[2];   // [14,64] i32
    const int*   unseen = (const int*)  d_in[3];   // [1200] i32
    const int*   seen   = (const int*)  d_in[4];   // [4800] i32
    float* out = (float*)d_out;

    setup_kernel<<<1, 1024>>>(gc);
    norm_kernel<<<N_CLASSES, 256>>>(attr, betas);

    // fused write pass: grid.x = ceil(6000/32) = 188 (covers all regions)
    write_kernel<<<dim3((N_CLASSES + 31) / 32, ATT / 32, 3), 256>>>(
        attr, betas, unseen, seen, out);
}

// round 7
// speedup vs baseline: 2.7446x; 1.2382x over previous
#include <cuda_runtime.h>
#include <stdint.h>

// ---------------- problem constants ----------------
#define N_CLASSES 6000
#define ATT       1024
#define G         15
#define GM1       14          // groups actually written (k=1..14 -> variants 2..15)
#define LP1       16          // rows per class
#define GSIZE     64
#define N_UNSEEN  1200
#define N_SEEN    4800

// ---------------- device scratch (no allocs allowed) ----------------
__device__ uint32_t d_mask16[ATT];            // bit v set => column in group of variant v (v=2..15)
__device__ int      d_nd[LP1];                // distinct masked column count per variant
__device__ float    d_inv[N_CLASSES * LP1];   // 1/norm per (class, variant)

// ---------------- kernel A: build column mask + distinct counts ----------------
__global__ void setup_kernel(const int* __restrict__ gc)
{
    __shared__ uint32_t mask_s[ATT];
    __shared__ int      cnt_s[LP1];

    int tid = threadIdx.x;                   // 1024 threads
    mask_s[tid] = 0u;
    if (tid < LP1) cnt_s[tid] = 0;
    __syncthreads();

    if (tid < GM1 * GSIZE) {
        int k   = tid >> 6;                  // group 0..13 -> variant k+2
        int col = gc[tid];
        atomicOr(&mask_s[col], 1u << (k + 2));
    }
    __syncthreads();

    uint32_t m = mask_s[tid];
    d_mask16[tid] = m;
    // count distinct masked columns per variant via shared atomics (<=896 adds)
    uint32_t mb = m >> 2;
    while (mb) {
        int s = __ffs(mb) - 1;
        atomicAdd(&cnt_s[s + 2], 1);
        mb &= mb - 1;
    }
    __syncthreads();
    if (tid < LP1) d_nd[tid] = (tid >= 2) ? cnt_s[tid] : 0;
}

// ---------------- kernel B: per-(class,variant) inverse norms ----------------
// ||row_v||^2 = sum(a^2) - sum_{masked cols} a^2 + n_distinct * beta^2
__global__ __launch_bounds__(256) void norm_kernel(const float* __restrict__ attr,
                                                   const float* __restrict__ betas)
{
    const int c    = blockIdx.x;
    const int tid  = threadIdx.x;            // 256 threads
    const int lane = tid & 31;
    const int w    = tid >> 5;               // 8 warps

    // each thread handles 4 consecutive columns via one float4 + one uint4
    const float4   x4 = __ldg((const float4*)(attr + (size_t)c * ATT) + tid);
    const uint4    m4 = *((const uint4*)d_mask16 + tid);

    float vals[15];                           // [0..13]=masked sums, [14]=total
    #pragma unroll
    for (int s = 0; s < 15; s++) vals[s] = 0.f;

    const float xs[4] = {x4.x * x4.x, x4.y * x4.y, x4.z * x4.z, x4.w * x4.w};
    const uint32_t ms[4] = {m4.x >> 2, m4.y >> 2, m4.z >> 2, m4.w >> 2};
    #pragma unroll
    for (int e = 0; e < 4; e++) {
        vals[14] += xs[e];
        uint32_t mb = ms[e];
        #pragma unroll
        for (int s = 0; s < GM1; s++)
            if ((mb >> s) & 1u) vals[s] += xs[e];
    }

    // warp reduction of all 15 values
    #pragma unroll
    for (int off = 16; off; off >>= 1)
        #pragma unroll
        for (int s = 0; s < 15; s++)
            vals[s] += __shfl_xor_sync(0xffffffffu, vals[s], off);

    __shared__ float red[8][16];
    if (lane == 0) {
        #pragma unroll
        for (int s = 0; s < 15; s++) red[w][s] = vals[s];
    }
    __syncthreads();

    if (tid < LP1) {
        float tot = 0.f, msum = 0.f;
        #pragma unroll
        for (int ww = 0; ww < 8; ww++) {
            tot += red[ww][14];
            if (tid >= 2) msum += red[ww][tid - 2];
        }
        float n2;
        if (tid < 2) {
            n2 = tot;
        } else {
            float b = __ldg(betas + (tid - 2));
            n2 = tot - msum + (float)d_nd[tid] * b * b;
        }
        n2 = fmaxf(n2, 0.f);
        float nrm = fmaxf(sqrtf(n2), 1e-12f);
        d_inv[(size_t)c * LP1 + tid] = 1.f / nrm;
    }
}

// ---------------- kernel C: tiled transposed write pass (fused 3 regions) ----
// Block = 32 positions x 32 attribute columns. Stage attr tile + inv tile in
// smem with coalesced loads, then write fully-coalesced float4 runs along the
// contiguous (pos,variant) output dimension. blockIdx.z selects the region
// (0=zsl, 1=seen, 2=gzsl). 1200 and 6000 are NOT multiples of 32 -> guards.
__global__ __launch_bounds__(256) void write_kernel(
        const float* __restrict__ attr,
        const float* __restrict__ betas,
        const int*   __restrict__ unseen,
        const int*   __restrict__ seen,
        float*       __restrict__ out)
{
    int npos;
    const int* classes;
    float* base;
    if (blockIdx.z == 0) {
        npos = N_UNSEEN; classes = unseen; base = out;
    } else if (blockIdx.z == 1) {
        npos = N_SEEN;   classes = seen;
        base = out + (size_t)ATT * N_UNSEEN * LP1;
    } else {
        npos = N_CLASSES; classes = nullptr;
        base = out + (size_t)ATT * (N_UNSEEN + N_SEEN) * LP1;
    }
    const int pos0 = blockIdx.x * 32;
    if (pos0 >= npos) return;                 // oversized grid.x for small regions
    const int a0   = blockIdx.y * 32;

    __shared__ int      cls_s[32];
    __shared__ float    attr_s[32][33];      // [pos_local][a_local], padded
    __shared__ float    inv_s[32][16];       // [pos_local][variant]
    __shared__ float    bv_s[16];
    __shared__ uint32_t mb_s[32];

    const int tid  = threadIdx.x;
    const int lane = tid & 31;
    const int w    = tid >> 5;               // warp 0..7

    if (tid < 32) {
        int p = pos0 + tid;
        int c = 0;                           // clamp OOB slots to class 0 (staging only)
        if (p < npos) c = classes ? __ldg(classes + p) : p;
        cls_s[tid] = c;
        mb_s[tid]  = d_mask16[a0 + tid];
    }
    if (tid < 16) bv_s[tid] = (tid >= 2) ? __ldg(betas + (tid - 2)) : 0.f;
    __syncthreads();

    // stage attribute tile: warp w loads rows p = i*8 + w (coalesced 128B)
    #pragma unroll
    for (int i = 0; i < 4; i++) {
        int p = i * 8 + w;
        int c = cls_s[p];
        attr_s[p][lane] = __ldg(attr + (size_t)c * ATT + a0 + lane);
    }
    // stage inv tile: 512 floats, 2 per thread (16-float segments)
    #pragma unroll
    for (int i = 0; i < 2; i++) {
        int t = i * 256 + tid;
        int p = t >> 4, v = t & 15;
        inv_s[p][v] = d_inv[(size_t)cls_s[p] * LP1 + v];
    }
    __syncthreads();

    // write: warp w handles a_local in [4w, 4w+4). For each a, the 32-pos
    // block covers 512 contiguous floats = 128 float4 (4 iters x 32 lanes).
    #pragma unroll
    for (int ai = 0; ai < 4; ai++) {
        const int al = w * 4 + ai;
        const int a  = a0 + al;
        const uint32_t mb = mb_s[al];
        float4* orow = (float4*)(base + (size_t)a * ((size_t)npos * LP1)
                                      + (size_t)pos0 * LP1);
        #pragma unroll
        for (int it = 0; it < 4; it++) {
            const int f4 = it * 32 + lane;
            const int pl = f4 >> 2;          // pos local 0..31
            const int q  = f4 & 3;           // variant quarter
            if (pos0 + pl < npos) {          // partial-tile guard
                const float av = attr_s[pl][al];
                float4 iv = *(const float4*)&inv_s[pl][q * 4];
                float ivv[4] = {iv.x, iv.y, iv.z, iv.w};
                float r[4];
                #pragma unroll
                for (int s = 0; s < 4; s++) {
                    int v = q * 4 + s;
                    r[s] = (((mb >> v) & 1u) ? bv_s[v] : av) * ivv[s];
                }
                float4 wv; wv.x = r[0]; wv.y = r[1]; wv.z = r[2]; wv.w = r[3];
                __stcs(&orow[f4], wv);       // streaming store: never re-read
            }
        }
    }
}

// ---------------- launcher ----------------
extern "C" void kernel_launch(void* const* d_in, const int* in_sizes, int n_in,
                              void* d_out, int out_size)
{
    const float* attr   = (const float*)d_in[0];   // [6000,1024] f32
    const float* betas  = (const float*)d_in[1];   // [1,15] f32 (first 14 used)
    const int*   gc     = (const int*)  d_in[2];   // [14,64] i32
    const int*   unseen = (const int*)  d_in[3];   // [1200] i32
    const int*   seen   = (const int*)  d_in[4];   // [4800] i32
    float* out = (float*)d_out;

    setup_kernel<<<1, 1024>>>(gc);
    norm_kernel<<<N_CLASSES, 256>>>(attr, betas);

    // fused write pass: grid.x = ceil(6000/32) = 188 (covers all regions)
    write_kernel<<<dim3((N_CLASSES + 31) / 32, ATT / 32, 3), 256>>>(
        attr, betas, unseen, seen, out);
}